// round 7
// baseline (speedup 1.0000x reference)
#include <cuda_runtime.h>
#include <cuda_bf16.h>
#include <cstdint>

// Problem constants (match reference setup_inputs)
#define T_TABLES 8
#define N_ROWS   100000
#define EMB_D    128
#define N_BAGS_B 8192

#define CTAS_PER_SM 8
#define NUM_SMS     148
#define CTAS        (NUM_SMS * CTAS_PER_SM)   // 1184
#define THREADS     128                       // 4 warps per CTA -> 32 warps/SM

// Persistent kernel: each warp grid-strides over bags.
// Lane l owns floats [4l, 4l+4) of the D=128 row.
__global__ __launch_bounds__(THREADS, CTAS_PER_SM) void emb_bag_kernel(
    const int* __restrict__ indices,
    const int* __restrict__ offsets,
    const float* __restrict__ weights,
    float* __restrict__ out)
{
    const int lane        = threadIdx.x & 31;
    const int warp0       = (blockIdx.x * THREADS + threadIdx.x) >> 5;
    const int total_warps = (CTAS * THREADS) >> 5;   // 4736, same as R4
    const int num_bags    = T_TABLES * N_BAGS_B;

    const char* __restrict__ wbytes =
        (const char*)weights + (unsigned)lane * 16u;

    int bag = warp0;
    if (bag >= num_bags) return;

    // Prefetch state for the first bag handled by this warp.
    int pf_start = offsets[bag];
    int pf_end   = offsets[bag + 1];
    int pf_idx   = (lane < pf_end - pf_start) ? indices[pf_start + lane] : 0;

    while (bag < num_bags) {
        const int t     = bag / N_BAGS_B;
        const int b     = bag - t * N_BAGS_B;
        const int start = pf_start;
        const int end   = pf_end;
        int       myidx = pf_idx;

        // Issue next bag's index/offset loads early so their latency hides
        // under this bag's gather burst.
        const int next_bag = bag + total_warps;
        if (next_bag < num_bags) {
            pf_start = offsets[next_bag];
            pf_end   = offsets[next_bag + 1];
            pf_idx   = (lane < pf_end - pf_start) ? indices[pf_start + lane] : 0;
        }

        // Table base: 64-bit once per bag; per-row offset is 32-bit (<51.2MB).
        const char* __restrict__ wbase =
            wbytes + (long long)t * (N_ROWS * EMB_D * 4ll);

        float4 acc = make_float4(0.f, 0.f, 0.f, 0.f);

        const int n0 = end - start;
        if (n0 == 32) {
            // Deep-MLP path: 4 independent accumulator chains decouple load
            // groups; with the 128-reg budget ptxas can keep ~20+ LDG.128
            // in flight per warp.
            float4 acc2 = make_float4(0.f, 0.f, 0.f, 0.f);
            float4 acc3 = make_float4(0.f, 0.f, 0.f, 0.f);
            float4 acc4 = make_float4(0.f, 0.f, 0.f, 0.f);
            #pragma unroll
            for (int j = 0; j < 32; j += 4) {
                const unsigned r0 = (unsigned)__shfl_sync(0xffffffffu, myidx, j);
                const unsigned r1 = (unsigned)__shfl_sync(0xffffffffu, myidx, j + 1);
                const unsigned r2 = (unsigned)__shfl_sync(0xffffffffu, myidx, j + 2);
                const unsigned r3 = (unsigned)__shfl_sync(0xffffffffu, myidx, j + 3);
                const float4 v0 = __ldg((const float4*)(wbase + (r0 << 9)));
                const float4 v1 = __ldg((const float4*)(wbase + (r1 << 9)));
                const float4 v2 = __ldg((const float4*)(wbase + (r2 << 9)));
                const float4 v3 = __ldg((const float4*)(wbase + (r3 << 9)));
                acc.x  += v0.x; acc.y  += v0.y; acc.z  += v0.z; acc.w  += v0.w;
                acc2.x += v1.x; acc2.y += v1.y; acc2.z += v1.z; acc2.w += v1.w;
                acc3.x += v2.x; acc3.y += v2.y; acc3.z += v2.z; acc3.w += v2.w;
                acc4.x += v3.x; acc4.y += v3.y; acc4.z += v3.z; acc4.w += v3.w;
            }
            acc.x += acc2.x; acc.y += acc2.y; acc.z += acc2.z; acc.w += acc2.w;
            acc3.x += acc4.x; acc3.y += acc4.y; acc3.z += acc4.z; acc3.w += acc4.w;
            acc.x += acc3.x; acc.y += acc3.y; acc.z += acc3.z; acc.w += acc3.w;
        } else {
            // Generic path: bags longer/shorter than 32.
            int i = start;
            int cur = myidx;
            int n = min(32, end - i);
            while (n > 0) {
                for (int j = 0; j < n; ++j) {
                    const unsigned r = (unsigned)__shfl_sync(0xffffffffu, cur, j);
                    const float4 v = __ldg((const float4*)(wbase + (r << 9)));
                    acc.x += v.x; acc.y += v.y; acc.z += v.z; acc.w += v.w;
                }
                i += n;
                n = min(32, end - i);
                if (n > 0) cur = (lane < n) ? indices[i + lane] : 0;
            }
        }

        // Output layout: [B, T*D] feature-concatenated: out[b, t*D + d]
        float4* __restrict__ o =
            (float4*)(out + ((long long)b * T_TABLES + t) * EMB_D);
        o[lane] = acc;

        bag = next_bag;
    }
}

extern "C" void kernel_launch(void* const* d_in, const int* in_sizes, int n_in,
                              void* d_out, int out_size)
{
    const int*   indices = (const int*)d_in[0];
    const int*   offsets = (const int*)d_in[1];
    const float* weights = (const float*)d_in[2];
    float*       out     = (float*)d_out;

    emb_bag_kernel<<<CTAS, THREADS>>>(indices, offsets, weights, out);
}

// round 8
// speedup vs baseline: 1.0584x; 1.0584x over previous
#include <cuda_runtime.h>
#include <cuda_bf16.h>
#include <cstdint>

// Problem constants (match reference setup_inputs)
#define T_TABLES 8
#define N_ROWS   100000
#define EMB_D    128
#define N_BAGS_B 8192

#define CTAS_PER_SM 4
#define NUM_SMS     152        // GB300 (not 148 = B300)
#define CTAS        (NUM_SMS * CTAS_PER_SM)   // 608
#define THREADS     256        // 8 warps per CTA -> 32 warps/SM

// Persistent kernel: each warp grid-strides over bags.
// Lane l owns floats [4l, 4l+4) of the D=128 row.
__global__ __launch_bounds__(THREADS, CTAS_PER_SM) void emb_bag_kernel(
    const int* __restrict__ indices,
    const int* __restrict__ offsets,
    const float* __restrict__ weights,
    float* __restrict__ out)
{
    const int lane        = threadIdx.x & 31;
    const int warp0       = (blockIdx.x * THREADS + threadIdx.x) >> 5;
    const int total_warps = (CTAS * THREADS) >> 5;   // 4864
    const int num_bags    = T_TABLES * N_BAGS_B;

    const char* __restrict__ wbytes =
        (const char*)weights + (unsigned)lane * 16u;

    int bag = warp0;
    if (bag >= num_bags) return;

    // Prefetch state for the first bag handled by this warp.
    int pf_start = offsets[bag];
    int pf_end   = offsets[bag + 1];
    int pf_idx   = (lane < pf_end - pf_start) ? indices[pf_start + lane] : 0;

    while (bag < num_bags) {
        const int t     = bag / N_BAGS_B;
        const int b     = bag - t * N_BAGS_B;
        const int start = pf_start;
        const int end   = pf_end;
        int       myidx = pf_idx;

        // Issue next bag's index/offset loads early so their latency hides
        // under this bag's gather burst.
        const int next_bag = bag + total_warps;
        if (next_bag < num_bags) {
            pf_start = offsets[next_bag];
            pf_end   = offsets[next_bag + 1];
            pf_idx   = (lane < pf_end - pf_start) ? indices[pf_start + lane] : 0;
        }

        // Table base: 64-bit once per bag; per-row offset is 32-bit (<51.2MB).
        const char* __restrict__ wbase =
            wbytes + (long long)t * (N_ROWS * EMB_D * 4ll);

        float4 acc = make_float4(0.f, 0.f, 0.f, 0.f);

        const int n0 = end - start;
        if (n0 == 32) {
            #pragma unroll
            for (int j = 0; j < 32; ++j) {
                const unsigned r = (unsigned)__shfl_sync(0xffffffffu, myidx, j);
                const float4 v = __ldg((const float4*)(wbase + (r << 9)));
                acc.x += v.x; acc.y += v.y; acc.z += v.z; acc.w += v.w;
            }
        } else {
            // Generic path: bags longer/shorter than 32.
            int i = start;
            int cur = myidx;
            int n = min(32, end - i);
            while (n > 0) {
                for (int j = 0; j < n; ++j) {
                    const unsigned r = (unsigned)__shfl_sync(0xffffffffu, cur, j);
                    const float4 v = __ldg((const float4*)(wbase + (r << 9)));
                    acc.x += v.x; acc.y += v.y; acc.z += v.z; acc.w += v.w;
                }
                i += n;
                n = min(32, end - i);
                if (n > 0) cur = (lane < n) ? indices[i + lane] : 0;
            }
        }

        // Output layout: [B, T*D] feature-concatenated: out[b, t*D + d]
        float4* __restrict__ o =
            (float4*)(out + ((long long)b * T_TABLES + t) * EMB_D);
        o[lane] = acc;

        bag = next_bag;
    }
}

extern "C" void kernel_launch(void* const* d_in, const int* in_sizes, int n_in,
                              void* d_out, int out_size)
{
    const int*   indices = (const int*)d_in[0];
    const int*   offsets = (const int*)d_in[1];
    const float* weights = (const float*)d_in[2];
    float*       out     = (float*)d_out;

    emb_bag_kernel<<<CTAS, THREADS>>>(indices, offsets, weights, out);
}

// round 9
// speedup vs baseline: 1.0827x; 1.0230x over previous
#include <cuda_runtime.h>
#include <cuda_bf16.h>
#include <cstdint>

// Problem constants (match reference setup_inputs)
#define T_TABLES 8
#define N_ROWS   100000
#define EMB_D    128
#define N_BAGS_B 8192

#define CTAS_PER_SM 4
#define NUM_SMS     148
#define CTAS        (NUM_SMS * CTAS_PER_SM)   // 592  (measured best, R4)
#define THREADS     256                       // 8 warps per CTA -> 32 warps/SM

// Persistent kernel: each warp grid-strides over bags.
// Lane l owns floats [4l, 4l+4) of the D=128 row.
__global__ __launch_bounds__(THREADS, CTAS_PER_SM) void emb_bag_kernel(
    const int* __restrict__ indices,
    const int* __restrict__ offsets,
    const float* __restrict__ weights,
    float* __restrict__ out)
{
    const int lane        = threadIdx.x & 31;
    const int warp0       = (blockIdx.x * THREADS + threadIdx.x) >> 5;
    const int total_warps = (CTAS * THREADS) >> 5;   // 4736
    const int num_bags    = T_TABLES * N_BAGS_B;

    const char* __restrict__ wbytes =
        (const char*)weights + (unsigned)lane * 16u;

    int bag = warp0;
    if (bag >= num_bags) return;

    // Prefetch state for the first bag handled by this warp.
    int pf_start = __ldg(offsets + bag);
    int pf_end   = __ldg(offsets + bag + 1);
    int pf_idx   = (lane < pf_end - pf_start) ? __ldg(indices + pf_start + lane) : 0;

    while (bag < num_bags) {
        const int t     = bag / N_BAGS_B;
        const int b     = bag - t * N_BAGS_B;
        const int start = pf_start;
        const int end   = pf_end;
        int       myidx = pf_idx;

        // Issue next bag's index/offset loads early so their latency hides
        // under this bag's gather burst.
        const int next_bag = bag + total_warps;
        if (next_bag < num_bags) {
            pf_start = __ldg(offsets + next_bag);
            pf_end   = __ldg(offsets + next_bag + 1);
            pf_idx   = (lane < pf_end - pf_start) ? __ldg(indices + pf_start + lane) : 0;
        }

        // Table base: 64-bit once per bag; per-row offset is 32-bit (<51.2MB).
        const char* __restrict__ wbase =
            wbytes + (long long)t * (N_ROWS * EMB_D * 4ll);

        float4 acc = make_float4(0.f, 0.f, 0.f, 0.f);

        const int n0 = end - start;
        if (n0 == 32) {
            #pragma unroll
            for (int j = 0; j < 32; ++j) {
                const unsigned r = (unsigned)__shfl_sync(0xffffffffu, myidx, j);
                const float4 v = __ldg((const float4*)(wbase + (r << 9)));
                acc.x += v.x; acc.y += v.y; acc.z += v.z; acc.w += v.w;
            }
        } else {
            // Generic path: bags longer/shorter than 32.
            int i = start;
            int cur = myidx;
            int n = min(32, end - i);
            while (n > 0) {
                for (int j = 0; j < n; ++j) {
                    const unsigned r = (unsigned)__shfl_sync(0xffffffffu, cur, j);
                    const float4 v = __ldg((const float4*)(wbase + (r << 9)));
                    acc.x += v.x; acc.y += v.y; acc.z += v.z; acc.w += v.w;
                }
                i += n;
                n = min(32, end - i);
                if (n > 0) cur = (lane < n) ? __ldg(indices + i + lane) : 0;
            }
        }

        // Output layout: [B, T*D] feature-concatenated: out[b, t*D + d].
        // Streaming store: output has zero reuse — keep it from displacing
        // the active weight-table window in L2.
        float4* __restrict__ o =
            (float4*)(out + ((long long)b * T_TABLES + t) * EMB_D);
        __stcs(o + lane, acc);

        bag = next_bag;
    }
}

extern "C" void kernel_launch(void* const* d_in, const int* in_sizes, int n_in,
                              void* d_out, int out_size)
{
    const int*   indices = (const int*)d_in[0];
    const int*   offsets = (const int*)d_in[1];
    const float* weights = (const float*)d_in[2];
    float*       out     = (float*)d_out;

    emb_bag_kernel<<<CTAS, THREADS>>>(indices, offsets, weights, out);
}